// round 8
// baseline (speedup 1.0000x reference)
#include <cuda_runtime.h>

// Fused filtfilt (order-2 IIR) over 1024 rows x 32768 fp32 samples.
//
// - Reference's max-abs normalization cancels exactly (linear, zero state).
// - Poles |lambda|=0.577 -> 24-step warm-up => ~1.9e-6 state error (tol 1e-3).
// - State-space unroll-by-4: s_{t+4} = A^4 s_t + sum_j A^{3-j} g x_{t+j}.
// - WARP-AUTONOMOUS tiles: each warp owns a 1408-sample segment with its own
//   private smem window (incl. duplicated halo). Zero __syncthreads; all
//   ordering via __syncwarp. Warps flow through phases independently.
// - All smem access 16B-aligned float4 (LDS.128/STS.128), conflict-free.
//
// smem index m <-> raw-x index off0 + m, off0 = base - 32 (mult of 4)
//              <-> ext position t = m - 23

#define N        32768
#define PAD      9
#define NE       (N + 2 * PAD)        // 32786
#define ROWS     1024
#define WARM     24
#define CL       44
#define SEG      (CL * 32)            // 1408 samples per warp
#define NSEG     24                   // 24*1408 = 33792 >= NE
#define WARPS    4
#define THREADS  (WARPS * 32)
#define WWIN     (SEG + 48)           // 1456 floats (covers m <= tlen+46)
#define SMEM_FLOATS (WARPS * WWIN)    // 5824
#define MOFF     (WARM - 1)           // 23

struct C {
    float b0, na1, na2;
    float g3x, g3y;   // g        (h1)
    float g2x, g2y;   // A g      (h2)
    float g1x, g1y;   // A^2 g    (h3)
    float g0x, g0y;   // A^3 g
    float p2x, p2y;   // first row of A^2
    float p3x, p3y;   // first row of A^3
    float m00, m01, m10, m11; // A^4
};

__device__ __forceinline__ C make_coef(const float* __restrict__ b,
                                       const float* __restrict__ a) {
    C c;
    float ia0 = 1.0f / a[0];
    float b0 = b[0] * ia0, b1 = b[1] * ia0, b2 = b[2] * ia0;
    float na1 = -(a[1] * ia0), na2 = -(a[2] * ia0);
    float g0 = fmaf(na1, b0, b1);
    float g1 = fmaf(na2, b0, b2);
    float A2_00 = fmaf(na1, na1, na2), A2_01 = na1;
    float A2_10 = na2 * na1,           A2_11 = na2;
    float A3_00 = fmaf(A2_00, na1, A2_01 * na2), A3_01 = A2_00;
    float A3_10 = fmaf(A2_10, na1, A2_11 * na2), A3_11 = A2_10;
    c.m00 = fmaf(A3_00, na1, A3_01 * na2); c.m01 = A3_00;
    c.m10 = fmaf(A3_10, na1, A3_11 * na2); c.m11 = A3_10;
    c.g3x = g0;                          c.g3y = g1;
    c.g2x = fmaf(na1, g0, g1);           c.g2y = na2 * g0;
    c.g1x = fmaf(A2_00, g0, A2_01 * g1); c.g1y = fmaf(A2_10, g0, A2_11 * g1);
    c.g0x = fmaf(A3_00, g0, A3_01 * g1); c.g0y = fmaf(A3_10, g0, A3_11 * g1);
    c.p2x = A2_00; c.p2y = A2_01;
    c.p3x = A3_00; c.p3y = A3_01;
    c.b0 = b0; c.na1 = na1; c.na2 = na2;
    return c;
}

// x0 = earliest sample in filter time
__device__ __forceinline__ void warm4(const C& c, float x0, float x1,
                                      float x2, float x3,
                                      float& z0, float& z1) {
    float w0 = fmaf(c.g0x, x0, fmaf(c.g1x, x1, fmaf(c.g2x, x2, c.g3x * x3)));
    float w1 = fmaf(c.g0y, x0, fmaf(c.g1y, x1, fmaf(c.g2y, x2, c.g3y * x3)));
    float nz0 = fmaf(c.m00, z0, fmaf(c.m01, z1, w0));
    float nz1 = fmaf(c.m10, z0, fmaf(c.m11, z1, w1));
    z0 = nz0; z1 = nz1;
}

__device__ __forceinline__ void warm1(const C& c, float xv,
                                      float& z0, float& z1) {
    float nz0 = fmaf(c.na1, z0, fmaf(c.g3x, xv, z1));
    float nz1 = fmaf(c.na2, z0, c.g3y * xv);
    z0 = nz0; z1 = nz1;
}

__device__ __forceinline__ void step4(const C& c, float x0, float x1,
                                      float x2, float x3,
                                      float& z0, float& z1,
                                      float& y0, float& y1,
                                      float& y2, float& y3) {
    y0 = fmaf(c.b0, x0, z0);
    y1 = fmaf(c.b0, x1, fmaf(c.g3x, x0, fmaf(c.na1, z0, z1)));
    y2 = fmaf(c.b0, x2, fmaf(c.g3x, x1,
             fmaf(c.g2x, x0, fmaf(c.p2x, z0, c.p2y * z1))));
    y3 = fmaf(c.b0, x3, fmaf(c.g3x, x2, fmaf(c.g2x, x1,
             fmaf(c.g1x, x0, fmaf(c.p3x, z0, c.p3y * z1)))));
    warm4(c, x0, x1, x2, x3, z0, z1);
}

__device__ __forceinline__ void step1(const C& c, float xv,
                                      float& z0, float& z1, float& y) {
    y = fmaf(c.b0, xv, z0);
    warm1(c, xv, z0, z1);
}

__global__ __launch_bounds__(THREADS)
void filtfilt_kernel(const float* __restrict__ x,
                     const float* __restrict__ bc,
                     const float* __restrict__ ac,
                     float* __restrict__ out) {
    __shared__ float sm[SMEM_FLOATS];

    const int lane = threadIdx.x & 31;
    const int wid  = threadIdx.x >> 5;
    const int row  = blockIdx.y;
    const int seg  = blockIdx.x * WARPS + wid;   // 0..23
    const int base = seg * SEG;
    const int tlen = min(SEG, NE - base);
    const int off0 = base - (WARM + PAD - 1);    // base - 32, mult of 4

    float*  ws  = sm + wid * WWIN;               // warp-private window
    float4* ws4 = (float4*)ws;

    const float* xr   = x   + (size_t)row * N;
    float*       outr = out + (size_t)row * N;

    const C c = make_coef(bc, ac);

    // ---- Phase 0: load window ws[m] = x[off0 + m] (warp-local) ----
    if (off0 >= 0 && off0 + WWIN <= N) {
        const float4* __restrict__ src = (const float4*)(xr + off0);
        #pragma unroll 4
        for (int i = lane; i < WWIN / 4; i += 32) ws4[i] = src[i];
    } else {
        #pragma unroll 4
        for (int idx = lane; idx < WWIN; idx += 32) {
            int i = off0 + idx;
            float v;
            if (i < 0)       v = 2.0f * xr[0]     - xr[-i];
            else if (i >= N) v = 2.0f * xr[N - 1] - xr[2 * N - 2 - i];
            else             v = xr[i];
            ws[idx] = v;
        }
    }
    __syncwarp();

    // chunk [sbeg, e) in segment-relative ext coords; m(t) = t + MOFF
    const int s    = lane * CL + 1;
    const int sbeg = (lane == 0) ? 0 : s;
    const bool active = (sbeg < tlen);
    const int e = active ? min(s + CL, tlen) : sbeg;

    // ---- Phase F1: forward warm-up (state only, reads x) ----
    float z0 = 0.0f, z1 = 0.0f;
    if (active) {
        if (lane == 0) {
            if (base > 0) {                      // warm over m in [0, 23)
                #pragma unroll
                for (int g = 0; g < 5; ++g) {    // m 0..19
                    float4 f = ws4[g];
                    warm4(c, f.x, f.y, f.z, f.w, z0, z1);
                }
                warm1(c, ws[20], z0, z1);
                warm1(c, ws[21], z0, z1);
                warm1(c, ws[22], z0, z1);
            }                                    // base==0: exact zero state
        } else {
            const float4* p4 = ws4 + ((s - 1) >> 2);  // m = s-1, aligned
            #pragma unroll
            for (int g = 0; g < WARM / 4; ++g) {
                float4 f = p4[g];
                warm4(c, f.x, f.y, f.z, f.w, z0, z1);
            }
        }
    }
    __syncwarp();

    // ---- Phase F2: forward body in-place (+WARM tail by last active) ----
    if (active) {
        int ebody = e;
        if (e == tlen) ebody = min(e + WARM, NE - base);
        int t = sbeg;
        while (t < ebody && ((t + MOFF) & 3) != 0) {   // <=1 iter (lane 0)
            float y; step1(c, ws[t + MOFF], z0, z1, y); ws[t + MOFF] = y; ++t;
        }
        for (; t + 4 <= ebody; t += 4) {
            int mi = (t + MOFF) >> 2;
            float4 f = ws4[mi];
            float y0, y1, y2, y3;
            step4(c, f.x, f.y, f.z, f.w, z0, z1, y0, y1, y2, y3);
            ws4[mi] = make_float4(y0, y1, y2, y3);
        }
        for (; t < ebody; ++t) {
            float y; step1(c, ws[t + MOFF], z0, z1, y); ws[t + MOFF] = y;
        }
    }
    __syncwarp();

    // ---- Phase B1: backward warm-up (reads neighbor's y1; state only) ----
    z0 = 0.0f; z1 = 0.0f;
    if (active) {
        int u = min(e + WARM - 1, NE - base - 1);  // clamp = exact at seq end
        while (u >= e && ((u + MOFF) & 3) != 3) { warm1(c, ws[u + MOFF], z0, z1); --u; }
        for (; u - 3 >= e; u -= 4) {
            float4 f = ws4[(u + MOFF - 3) >> 2];
            warm4(c, f.w, f.z, f.y, f.x, z0, z1);  // descending time
        }
        for (; u >= e; --u) warm1(c, ws[u + MOFF], z0, z1);
    }
    __syncwarp();

    // ---- Phase B2: backward body in-place ----
    if (active) {
        int u = e - 1;
        while (u >= sbeg && ((u + MOFF) & 3) != 3) {
            float y; step1(c, ws[u + MOFF], z0, z1, y); ws[u + MOFF] = y; --u;
        }
        for (; u - 3 >= sbeg; u -= 4) {
            int mi = (u + MOFF - 3) >> 2;
            float4 f = ws4[mi];
            float y0, y1, y2, y3;
            step4(c, f.w, f.z, f.y, f.x, z0, z1, y0, y1, y2, y3);
            ws4[mi] = make_float4(y3, y2, y1, y0);
        }
        for (; u >= sbeg; --u) {
            float y; step1(c, ws[u + MOFF], z0, z1, y); ws[u + MOFF] = y;
        }
    }
    __syncwarp();

    // ---- Phase 5: store ws[m] -> outr[off0 + m]; clips implement the crop ----
    {
        int M0 = max(MOFF, -off0);                 // o >= 0  (left crop)
        int M1 = min(MOFF + tlen, N - off0);       // o < N   (right crop)
        int mA = (M0 + 3) & ~3;
        int mB = M1 & ~3;
        if (lane < mA - M0) { int m = M0 + lane; outr[off0 + m] = ws[m]; }
        if (lane < M1 - mB) { int m = mB + lane; outr[off0 + m] = ws[m]; }
        float4* dst4 = (float4*)(outr + off0);     // off0 mult of 4
        #pragma unroll 4
        for (int mi = (mA >> 2) + lane; mi < (mB >> 2); mi += 32)
            dst4[mi] = ws4[mi];
    }
}

extern "C" void kernel_launch(void* const* d_in, const int* in_sizes, int n_in,
                              void* d_out, int out_size) {
    const float* x = (const float*)d_in[0];
    const float* b = (const float*)d_in[1];
    const float* a = (const float*)d_in[2];
    float* out = (float*)d_out;

    dim3 grid(NSEG / WARPS, ROWS);                 // (6, 1024)
    filtfilt_kernel<<<grid, THREADS>>>(x, b, a, out);
}

// round 9
// speedup vs baseline: 1.1398x; 1.1398x over previous
#include <cuda_runtime.h>

// Fused filtfilt (order-2 IIR) over 1024 rows x 32768 fp32 samples.
//
// - Reference's max-abs normalization cancels exactly (linear, zero state).
// - Poles |lambda|=0.577 -> 24-step warm-up => ~1.9e-6 state error (tol 1e-3).
// - State-space unroll-by-4: s_{t+4} = A^4 s_t + sum_j A^{3-j} g x_{t+j}.
// - Warp-autonomous 1408-sample segments, private smem windows, __syncwarp only.
// - NEW: segments 1..22 (92% of work) take a fully-unrolled compile-time-exact
//   path: fixed trip counts, no dynamic bounds, no misalignment fixups ->
//   ptxas batches LDS.128s (MLP) and drops all loop ALU/branches.
//
// smem index m <-> raw-x index off0 + m, off0 = base - 32 (mult of 4)
//              <-> ext position t = m - 23

#define N        32768
#define PAD      9
#define NE       (N + 2 * PAD)        // 32786
#define ROWS     1024
#define WARM     24
#define CL       44
#define SEG      (CL * 32)            // 1408 samples per warp
#define NSEG     24                   // 24*1408 = 33792 >= NE
#define WARPS    4
#define THREADS  (WARPS * 32)
#define WWIN     (SEG + 48)           // 1456 floats
#define SMEM_FLOATS (WARPS * WWIN)    // 5824
#define MOFF     (WARM - 1)           // 23

struct C {
    float b0, na1, na2;
    float g3x, g3y;   // g        (h1)
    float g2x, g2y;   // A g      (h2)
    float g1x, g1y;   // A^2 g    (h3)
    float g0x, g0y;   // A^3 g
    float p2x, p2y;   // first row of A^2
    float p3x, p3y;   // first row of A^3
    float m00, m01, m10, m11; // A^4
};

__device__ __forceinline__ C make_coef(const float* __restrict__ b,
                                       const float* __restrict__ a) {
    C c;
    float ia0 = 1.0f / a[0];
    float b0 = b[0] * ia0, b1 = b[1] * ia0, b2 = b[2] * ia0;
    float na1 = -(a[1] * ia0), na2 = -(a[2] * ia0);
    float g0 = fmaf(na1, b0, b1);
    float g1 = fmaf(na2, b0, b2);
    float A2_00 = fmaf(na1, na1, na2), A2_01 = na1;
    float A2_10 = na2 * na1,           A2_11 = na2;
    float A3_00 = fmaf(A2_00, na1, A2_01 * na2), A3_01 = A2_00;
    float A3_10 = fmaf(A2_10, na1, A2_11 * na2), A3_11 = A2_10;
    c.m00 = fmaf(A3_00, na1, A3_01 * na2); c.m01 = A3_00;
    c.m10 = fmaf(A3_10, na1, A3_11 * na2); c.m11 = A3_10;
    c.g3x = g0;                          c.g3y = g1;
    c.g2x = fmaf(na1, g0, g1);           c.g2y = na2 * g0;
    c.g1x = fmaf(A2_00, g0, A2_01 * g1); c.g1y = fmaf(A2_10, g0, A2_11 * g1);
    c.g0x = fmaf(A3_00, g0, A3_01 * g1); c.g0y = fmaf(A3_10, g0, A3_11 * g1);
    c.p2x = A2_00; c.p2y = A2_01;
    c.p3x = A3_00; c.p3y = A3_01;
    c.b0 = b0; c.na1 = na1; c.na2 = na2;
    return c;
}

// x0 = earliest sample in filter time
__device__ __forceinline__ void warm4(const C& c, float x0, float x1,
                                      float x2, float x3,
                                      float& z0, float& z1) {
    float w0 = fmaf(c.g0x, x0, fmaf(c.g1x, x1, fmaf(c.g2x, x2, c.g3x * x3)));
    float w1 = fmaf(c.g0y, x0, fmaf(c.g1y, x1, fmaf(c.g2y, x2, c.g3y * x3)));
    float nz0 = fmaf(c.m00, z0, fmaf(c.m01, z1, w0));
    float nz1 = fmaf(c.m10, z0, fmaf(c.m11, z1, w1));
    z0 = nz0; z1 = nz1;
}

__device__ __forceinline__ void warm1(const C& c, float xv,
                                      float& z0, float& z1) {
    float nz0 = fmaf(c.na1, z0, fmaf(c.g3x, xv, z1));
    float nz1 = fmaf(c.na2, z0, c.g3y * xv);
    z0 = nz0; z1 = nz1;
}

__device__ __forceinline__ void step4(const C& c, float x0, float x1,
                                      float x2, float x3,
                                      float& z0, float& z1,
                                      float& y0, float& y1,
                                      float& y2, float& y3) {
    y0 = fmaf(c.b0, x0, z0);
    y1 = fmaf(c.b0, x1, fmaf(c.g3x, x0, fmaf(c.na1, z0, z1)));
    y2 = fmaf(c.b0, x2, fmaf(c.g3x, x1,
             fmaf(c.g2x, x0, fmaf(c.p2x, z0, c.p2y * z1))));
    y3 = fmaf(c.b0, x3, fmaf(c.g3x, x2, fmaf(c.g2x, x1,
             fmaf(c.g1x, x0, fmaf(c.p3x, z0, c.p3y * z1)))));
    warm4(c, x0, x1, x2, x3, z0, z1);
}

__device__ __forceinline__ void step1(const C& c, float xv,
                                      float& z0, float& z1, float& y) {
    y = fmaf(c.b0, xv, z0);
    warm1(c, xv, z0, z1);
}

__global__ __launch_bounds__(THREADS, 8)
void filtfilt_kernel(const float* __restrict__ x,
                     const float* __restrict__ bc,
                     const float* __restrict__ ac,
                     float* __restrict__ out) {
    __shared__ float sm[SMEM_FLOATS];

    const int lane = threadIdx.x & 31;
    const int wid  = threadIdx.x >> 5;
    const int row  = blockIdx.y;
    const int seg  = blockIdx.x * WARPS + wid;   // 0..23
    const int base = seg * SEG;
    const int off0 = base - (WARM + PAD - 1);    // base - 32, mult of 4

    float*  ws  = sm + wid * WWIN;               // warp-private window
    float4* ws4 = (float4*)ws;

    const float* xr   = x   + (size_t)row * N;
    float*       outr = out + (size_t)row * N;

    const C c = make_coef(bc, ac);

    if (seg >= 1 && seg <= 22) {
        // ================= FAST PATH: interior segment =================
        // Uniform layout: lane l's body = 11 groups ws4[11l+6 .. 11l+16]
        // (t in [44l+1, 44l+45)); warm = groups ws4[11l .. 11l+5].
        const int gb = 11 * lane;

        // ---- load window: 364 float4 per warp ----
        const float4* __restrict__ src = (const float4*)(xr + off0);
        #pragma unroll
        for (int i = 0; i < 11; ++i)
            ws4[lane + 32 * i] = src[lane + 32 * i];
        if (lane < 12) ws4[lane + 352] = src[lane + 352];
        __syncwarp();

        // ---- forward warm-up ----
        float z0 = 0.0f, z1 = 0.0f;
        #pragma unroll
        for (int g = 0; g < 5; ++g) {
            float4 f = ws4[gb + g];
            warm4(c, f.x, f.y, f.z, f.w, z0, z1);
        }
        if (lane == 0) {                 // stop before t=0 (m=23): body owns it
            warm1(c, ws[20], z0, z1);
            warm1(c, ws[21], z0, z1);
            warm1(c, ws[22], z0, z1);
        } else {
            float4 f = ws4[gb + 5];
            warm4(c, f.x, f.y, f.z, f.w, z0, z1);
        }
        __syncwarp();

        // ---- forward body (in-place x -> y1) ----
        if (lane == 0) {                 // t = 0 (m = 23)
            float y; step1(c, ws[23], z0, z1, y); ws[23] = y;
        }
        #pragma unroll
        for (int g = 6; g < 17; ++g) {
            float4 f = ws4[gb + g];
            float y0, y1, y2, y3;
            step4(c, f.x, f.y, f.z, f.w, z0, z1, y0, y1, y2, y3);
            ws4[gb + g] = make_float4(y0, y1, y2, y3);
        }
        if (lane == 31) {                // tail t 1409..1432 feeds B-warm
            #pragma unroll
            for (int g = 17; g < 23; ++g) {
                float4 f = ws4[gb + g];
                float y0, y1, y2, y3;
                step4(c, f.x, f.y, f.z, f.w, z0, z1, y0, y1, y2, y3);
                ws4[gb + g] = make_float4(y0, y1, y2, y3);
            }
        }
        __syncwarp();

        // ---- backward warm-up: groups ws4[gb+22 .. gb+17], time-descending ----
        z0 = 0.0f; z1 = 0.0f;
        #pragma unroll
        for (int g = 22; g > 16; --g) {
            float4 f = ws4[gb + g];
            warm4(c, f.w, f.z, f.y, f.x, z0, z1);
        }
        __syncwarp();

        // ---- backward body (in-place y1 -> y2) ----
        #pragma unroll
        for (int g = 16; g >= 6; --g) {
            float4 f = ws4[gb + g];
            float y0, y1, y2, y3;
            step4(c, f.w, f.z, f.y, f.x, z0, z1, y0, y1, y2, y3);
            ws4[gb + g] = make_float4(y3, y2, y1, y0);
        }
        if (lane == 0) {                 // t = 0 (m = 23)
            float y; step1(c, ws[23], z0, z1, y); ws[23] = y;
        }
        __syncwarp();

        // ---- store: m 23 scalar + groups ws4[6..357] (o = off0 + m) ----
        float4* dst4 = (float4*)(outr + off0);
        if (lane == 0) outr[off0 + 23] = ws[23];
        #pragma unroll
        for (int i = 0; i < 11; ++i) {
            int mi = 6 + lane + 32 * i;
            dst4[mi] = ws4[mi];
        }
    } else {
        // ================= GENERIC PATH: segments 0, 23 =================
        const int tlen = min(SEG, NE - base);

        // ---- Phase 0: load (mirror edges) ----
        #pragma unroll 4
        for (int idx = lane; idx < WWIN; idx += 32) {
            int i = off0 + idx;
            float v;
            if (i < 0)       v = 2.0f * xr[0]     - xr[-i];
            else if (i >= N) v = 2.0f * xr[N - 1] - xr[2 * N - 2 - i];
            else             v = xr[i];
            ws[idx] = v;
        }
        __syncwarp();

        const int s    = lane * CL + 1;
        const int sbeg = (lane == 0) ? 0 : s;
        const bool active = (sbeg < tlen);
        const int e = active ? min(s + CL, tlen) : sbeg;

        // ---- F1: forward warm-up ----
        float z0 = 0.0f, z1 = 0.0f;
        if (active) {
            if (lane == 0) {
                if (base > 0) {
                    #pragma unroll
                    for (int g = 0; g < 5; ++g) {
                        float4 f = ws4[g];
                        warm4(c, f.x, f.y, f.z, f.w, z0, z1);
                    }
                    warm1(c, ws[20], z0, z1);
                    warm1(c, ws[21], z0, z1);
                    warm1(c, ws[22], z0, z1);
                }                         // base==0: exact zero state
            } else {
                const float4* p4 = ws4 + ((s - 1) >> 2);
                #pragma unroll
                for (int g = 0; g < WARM / 4; ++g) {
                    float4 f = p4[g];
                    warm4(c, f.x, f.y, f.z, f.w, z0, z1);
                }
            }
        }
        __syncwarp();

        // ---- F2: forward body in-place (+WARM tail by last active) ----
        if (active) {
            int ebody = e;
            if (e == tlen) ebody = min(e + WARM, NE - base);
            int t = sbeg;
            while (t < ebody && ((t + MOFF) & 3) != 0) {
                float y; step1(c, ws[t + MOFF], z0, z1, y); ws[t + MOFF] = y; ++t;
            }
            for (; t + 4 <= ebody; t += 4) {
                int mi = (t + MOFF) >> 2;
                float4 f = ws4[mi];
                float y0, y1, y2, y3;
                step4(c, f.x, f.y, f.z, f.w, z0, z1, y0, y1, y2, y3);
                ws4[mi] = make_float4(y0, y1, y2, y3);
            }
            for (; t < ebody; ++t) {
                float y; step1(c, ws[t + MOFF], z0, z1, y); ws[t + MOFF] = y;
            }
        }
        __syncwarp();

        // ---- B1: backward warm-up ----
        z0 = 0.0f; z1 = 0.0f;
        if (active) {
            int u = min(e + WARM - 1, NE - base - 1);
            while (u >= e && ((u + MOFF) & 3) != 3) { warm1(c, ws[u + MOFF], z0, z1); --u; }
            for (; u - 3 >= e; u -= 4) {
                float4 f = ws4[(u + MOFF - 3) >> 2];
                warm4(c, f.w, f.z, f.y, f.x, z0, z1);
            }
            for (; u >= e; --u) warm1(c, ws[u + MOFF], z0, z1);
        }
        __syncwarp();

        // ---- B2: backward body in-place ----
        if (active) {
            int u = e - 1;
            while (u >= sbeg && ((u + MOFF) & 3) != 3) {
                float y; step1(c, ws[u + MOFF], z0, z1, y); ws[u + MOFF] = y; --u;
            }
            for (; u - 3 >= sbeg; u -= 4) {
                int mi = (u + MOFF - 3) >> 2;
                float4 f = ws4[mi];
                float y0, y1, y2, y3;
                step4(c, f.w, f.z, f.y, f.x, z0, z1, y0, y1, y2, y3);
                ws4[mi] = make_float4(y3, y2, y1, y0);
            }
            for (; u >= sbeg; --u) {
                float y; step1(c, ws[u + MOFF], z0, z1, y); ws[u + MOFF] = y;
            }
        }
        __syncwarp();

        // ---- store ----
        {
            int M0 = max(MOFF, -off0);
            int M1 = min(MOFF + tlen, N - off0);
            int mA = (M0 + 3) & ~3;
            int mB = M1 & ~3;
            if (lane < mA - M0) { int m = M0 + lane; outr[off0 + m] = ws[m]; }
            if (lane < M1 - mB) { int m = mB + lane; outr[off0 + m] = ws[m]; }
            float4* dst4 = (float4*)(outr + off0);
            #pragma unroll 4
            for (int mi = (mA >> 2) + lane; mi < (mB >> 2); mi += 32)
                dst4[mi] = ws4[mi];
        }
    }
}

extern "C" void kernel_launch(void* const* d_in, const int* in_sizes, int n_in,
                              void* d_out, int out_size) {
    const float* x = (const float*)d_in[0];
    const float* b = (const float*)d_in[1];
    const float* a = (const float*)d_in[2];
    float* out = (float*)d_out;

    dim3 grid(NSEG / WARPS, ROWS);                 // (6, 1024)
    filtfilt_kernel<<<grid, THREADS>>>(x, b, a, out);
}

// round 10
// speedup vs baseline: 1.2501x; 1.0968x over previous
#include <cuda_runtime.h>
#include <cuda_pipeline.h>

// Fused filtfilt (order-2 IIR) over 1024 rows x 32768 fp32 samples.
//
// - Reference's max-abs normalization cancels exactly (linear, zero state).
// - Poles |lambda|=0.577 -> 24-step warm-up => ~1.9e-6 state error (tol 1e-3).
// - State-space unroll-by-4: s_{t+4} = A^4 s_t + sum_j A^{3-j} g x_{t+j}.
// - Warp-autonomous 1408-sample segments; fully-unrolled fast path interior.
// - NEW (R9): persistent warps. Each warp owns 6 consecutive segments of its
//   row and double-buffers them via cp.async: prefetch seg k+1 while
//   computing seg k. Keeps ~48 sectors/warp in flight DURING compute ->
//   DRAM stays saturated instead of burst-idle-burst. 1 block per row.

#define N        32768
#define PAD      9
#define NE       (N + 2 * PAD)        // 32786
#define ROWS     1024
#define WARM     24
#define CL       44
#define SEG      (CL * 32)            // 1408
#define NSEG     24
#define WARPS    4
#define THREADS  (WARPS * 32)
#define SPW      (NSEG / WARPS)       // 6 segments per warp
#define WWIN     (SEG + 48)           // 1456 floats per buffer
#define MOFF     (WARM - 1)           // 23

struct C {
    float b0, na1, na2;
    float g3x, g3y, g2x, g2y, g1x, g1y, g0x, g0y;
    float p2x, p2y, p3x, p3y;
    float m00, m01, m10, m11;
};

__device__ __forceinline__ C make_coef(const float* __restrict__ b,
                                       const float* __restrict__ a) {
    C c;
    float ia0 = 1.0f / a[0];
    float b0 = b[0] * ia0, b1 = b[1] * ia0, b2 = b[2] * ia0;
    float na1 = -(a[1] * ia0), na2 = -(a[2] * ia0);
    float g0 = fmaf(na1, b0, b1);
    float g1 = fmaf(na2, b0, b2);
    float A2_00 = fmaf(na1, na1, na2), A2_01 = na1;
    float A2_10 = na2 * na1,           A2_11 = na2;
    float A3_00 = fmaf(A2_00, na1, A2_01 * na2), A3_01 = A2_00;
    float A3_10 = fmaf(A2_10, na1, A2_11 * na2), A3_11 = A2_10;
    c.m00 = fmaf(A3_00, na1, A3_01 * na2); c.m01 = A3_00;
    c.m10 = fmaf(A3_10, na1, A3_11 * na2); c.m11 = A3_10;
    c.g3x = g0;                          c.g3y = g1;
    c.g2x = fmaf(na1, g0, g1);           c.g2y = na2 * g0;
    c.g1x = fmaf(A2_00, g0, A2_01 * g1); c.g1y = fmaf(A2_10, g0, A2_11 * g1);
    c.g0x = fmaf(A3_00, g0, A3_01 * g1); c.g0y = fmaf(A3_10, g0, A3_11 * g1);
    c.p2x = A2_00; c.p2y = A2_01;
    c.p3x = A3_00; c.p3y = A3_01;
    c.b0 = b0; c.na1 = na1; c.na2 = na2;
    return c;
}

__device__ __forceinline__ void warm4(const C& c, float x0, float x1,
                                      float x2, float x3,
                                      float& z0, float& z1) {
    float w0 = fmaf(c.g0x, x0, fmaf(c.g1x, x1, fmaf(c.g2x, x2, c.g3x * x3)));
    float w1 = fmaf(c.g0y, x0, fmaf(c.g1y, x1, fmaf(c.g2y, x2, c.g3y * x3)));
    float nz0 = fmaf(c.m00, z0, fmaf(c.m01, z1, w0));
    float nz1 = fmaf(c.m10, z0, fmaf(c.m11, z1, w1));
    z0 = nz0; z1 = nz1;
}

__device__ __forceinline__ void warm1(const C& c, float xv,
                                      float& z0, float& z1) {
    float nz0 = fmaf(c.na1, z0, fmaf(c.g3x, xv, z1));
    float nz1 = fmaf(c.na2, z0, c.g3y * xv);
    z0 = nz0; z1 = nz1;
}

__device__ __forceinline__ void step4(const C& c, float x0, float x1,
                                      float x2, float x3,
                                      float& z0, float& z1,
                                      float& y0, float& y1,
                                      float& y2, float& y3) {
    y0 = fmaf(c.b0, x0, z0);
    y1 = fmaf(c.b0, x1, fmaf(c.g3x, x0, fmaf(c.na1, z0, z1)));
    y2 = fmaf(c.b0, x2, fmaf(c.g3x, x1,
             fmaf(c.g2x, x0, fmaf(c.p2x, z0, c.p2y * z1))));
    y3 = fmaf(c.b0, x3, fmaf(c.g3x, x2, fmaf(c.g2x, x1,
             fmaf(c.g1x, x0, fmaf(c.p3x, z0, c.p3y * z1)))));
    warm4(c, x0, x1, x2, x3, z0, z1);
}

__device__ __forceinline__ void step1(const C& c, float xv,
                                      float& z0, float& z1, float& y) {
    y = fmaf(c.b0, xv, z0);
    warm1(c, xv, z0, z1);
}

// Direct (synchronous) fill with odd-extension mirrors — edge segments only.
__device__ __forceinline__ void fill_direct(float* ws, const float* __restrict__ xr,
                                            int off0, int lane) {
    #pragma unroll 4
    for (int idx = lane; idx < WWIN; idx += 32) {
        int i = off0 + idx;
        float v;
        if (i < 0)       v = 2.0f * xr[0]     - xr[-i];
        else if (i >= N) v = 2.0f * xr[N - 1] - xr[2 * N - 2 - i];
        else             v = xr[i];
        ws[idx] = v;
    }
}

// Fully-unrolled compute for interior segments (1..22). R8-validated.
__device__ __forceinline__ void compute_fast(float* ws, int lane, const C& c,
                                             float* __restrict__ outr, int off0) {
    float4* ws4 = (float4*)ws;
    const int gb = 11 * lane;

    // forward warm-up
    float z0 = 0.0f, z1 = 0.0f;
    #pragma unroll
    for (int g = 0; g < 5; ++g) {
        float4 f = ws4[gb + g];
        warm4(c, f.x, f.y, f.z, f.w, z0, z1);
    }
    if (lane == 0) {
        warm1(c, ws[20], z0, z1);
        warm1(c, ws[21], z0, z1);
        warm1(c, ws[22], z0, z1);
    } else {
        float4 f = ws4[gb + 5];
        warm4(c, f.x, f.y, f.z, f.w, z0, z1);
    }
    __syncwarp();

    // forward body (in-place x -> y1)
    if (lane == 0) { float y; step1(c, ws[23], z0, z1, y); ws[23] = y; }
    #pragma unroll
    for (int g = 6; g < 17; ++g) {
        float4 f = ws4[gb + g];
        float y0, y1, y2, y3;
        step4(c, f.x, f.y, f.z, f.w, z0, z1, y0, y1, y2, y3);
        ws4[gb + g] = make_float4(y0, y1, y2, y3);
    }
    if (lane == 31) {                  // tail feeds backward warm-up
        #pragma unroll
        for (int g = 17; g < 23; ++g) {
            float4 f = ws4[gb + g];
            float y0, y1, y2, y3;
            step4(c, f.x, f.y, f.z, f.w, z0, z1, y0, y1, y2, y3);
            ws4[gb + g] = make_float4(y0, y1, y2, y3);
        }
    }
    __syncwarp();

    // backward warm-up (time-descending)
    z0 = 0.0f; z1 = 0.0f;
    #pragma unroll
    for (int g = 22; g > 16; --g) {
        float4 f = ws4[gb + g];
        warm4(c, f.w, f.z, f.y, f.x, z0, z1);
    }
    __syncwarp();

    // backward body (in-place y1 -> y2)
    #pragma unroll
    for (int g = 16; g >= 6; --g) {
        float4 f = ws4[gb + g];
        float y0, y1, y2, y3;
        step4(c, f.w, f.z, f.y, f.x, z0, z1, y0, y1, y2, y3);
        ws4[gb + g] = make_float4(y3, y2, y1, y0);
    }
    if (lane == 0) { float y; step1(c, ws[23], z0, z1, y); ws[23] = y; }
    __syncwarp();

    // store
    float4* dst4 = (float4*)(outr + off0);
    if (lane == 0) outr[off0 + 23] = ws[23];
    #pragma unroll
    for (int i = 0; i < 11; ++i) {
        int mi = 6 + lane + 32 * i;
        dst4[mi] = ws4[mi];
    }
}

// Generic compute for edge segments (0, 23). R8-validated.
__device__ __forceinline__ void compute_generic(float* ws, int lane, const C& c,
                                                float* __restrict__ outr,
                                                int base, int off0) {
    float4* ws4 = (float4*)ws;
    const int tlen = min(SEG, NE - base);

    const int s    = lane * CL + 1;
    const int sbeg = (lane == 0) ? 0 : s;
    const bool active = (sbeg < tlen);
    const int e = active ? min(s + CL, tlen) : sbeg;

    float z0 = 0.0f, z1 = 0.0f;
    if (active) {
        if (lane == 0) {
            if (base > 0) {
                #pragma unroll
                for (int g = 0; g < 5; ++g) {
                    float4 f = ws4[g];
                    warm4(c, f.x, f.y, f.z, f.w, z0, z1);
                }
                warm1(c, ws[20], z0, z1);
                warm1(c, ws[21], z0, z1);
                warm1(c, ws[22], z0, z1);
            }                            // base==0: exact zero state
        } else {
            const float4* p4 = ws4 + ((s - 1) >> 2);
            #pragma unroll
            for (int g = 0; g < WARM / 4; ++g) {
                float4 f = p4[g];
                warm4(c, f.x, f.y, f.z, f.w, z0, z1);
            }
        }
    }
    __syncwarp();

    if (active) {
        int ebody = e;
        if (e == tlen) ebody = min(e + WARM, NE - base);
        int t = sbeg;
        while (t < ebody && ((t + MOFF) & 3) != 0) {
            float y; step1(c, ws[t + MOFF], z0, z1, y); ws[t + MOFF] = y; ++t;
        }
        for (; t + 4 <= ebody; t += 4) {
            int mi = (t + MOFF) >> 2;
            float4 f = ws4[mi];
            float y0, y1, y2, y3;
            step4(c, f.x, f.y, f.z, f.w, z0, z1, y0, y1, y2, y3);
            ws4[mi] = make_float4(y0, y1, y2, y3);
        }
        for (; t < ebody; ++t) {
            float y; step1(c, ws[t + MOFF], z0, z1, y); ws[t + MOFF] = y;
        }
    }
    __syncwarp();

    z0 = 0.0f; z1 = 0.0f;
    if (active) {
        int u = min(e + WARM - 1, NE - base - 1);
        while (u >= e && ((u + MOFF) & 3) != 3) { warm1(c, ws[u + MOFF], z0, z1); --u; }
        for (; u - 3 >= e; u -= 4) {
            float4 f = ws4[(u + MOFF - 3) >> 2];
            warm4(c, f.w, f.z, f.y, f.x, z0, z1);
        }
        for (; u >= e; --u) warm1(c, ws[u + MOFF], z0, z1);
    }
    __syncwarp();

    if (active) {
        int u = e - 1;
        while (u >= sbeg && ((u + MOFF) & 3) != 3) {
            float y; step1(c, ws[u + MOFF], z0, z1, y); ws[u + MOFF] = y; --u;
        }
        for (; u - 3 >= sbeg; u -= 4) {
            int mi = (u + MOFF - 3) >> 2;
            float4 f = ws4[mi];
            float y0, y1, y2, y3;
            step4(c, f.w, f.z, f.y, f.x, z0, z1, y0, y1, y2, y3);
            ws4[mi] = make_float4(y3, y2, y1, y0);
        }
        for (; u >= sbeg; --u) {
            float y; step1(c, ws[u + MOFF], z0, z1, y); ws[u + MOFF] = y;
        }
    }
    __syncwarp();

    {
        int M0 = max(MOFF, -off0);
        int M1 = min(MOFF + tlen, N - off0);
        int mA = (M0 + 3) & ~3;
        int mB = M1 & ~3;
        if (lane < mA - M0) { int m = M0 + lane; outr[off0 + m] = ws[m]; }
        if (lane < M1 - mB) { int m = mB + lane; outr[off0 + m] = ws[m]; }
        float4* dst4 = (float4*)(outr + off0);
        #pragma unroll 4
        for (int mi = (mA >> 2) + lane; mi < (mB >> 2); mi += 32)
            dst4[mi] = ws4[mi];
    }
}

__global__ __launch_bounds__(THREADS, 4)
void filtfilt_kernel(const float* __restrict__ x,
                     const float* __restrict__ bc,
                     const float* __restrict__ ac,
                     float* __restrict__ out) {
    __shared__ float sm[WARPS * 2 * WWIN];        // 46.6 KB

    const int lane = threadIdx.x & 31;
    const int wid  = threadIdx.x >> 5;
    const int row  = blockIdx.x;

    const float* xr   = x   + (size_t)row * N;
    float*       outr = out + (size_t)row * N;

    const C c = make_coef(bc, ac);

    float* buf0 = sm + wid * (2 * WWIN);
    float* buf1 = buf0 + WWIN;

    // prefetch helper: segment q of this warp -> buffer b
    auto prefetch = [&](int q, float* buf) {
        const int seg  = wid * SPW + q;
        const int off0 = seg * SEG - 32;
        if (seg >= 1 && seg <= 22) {
            const float4* __restrict__ src = (const float4*)(xr + off0);
            float4* dst = (float4*)buf;
            #pragma unroll
            for (int i = 0; i < 11; ++i)
                __pipeline_memcpy_async(&dst[lane + 32 * i],
                                        &src[lane + 32 * i], 16);
            if (lane < 12)
                __pipeline_memcpy_async(&dst[lane + 352], &src[lane + 352], 16);
        } else {
            fill_direct(buf, xr, off0, lane);     // sync fill, mirrors
        }
        __pipeline_commit();                       // one group per segment
    };

    prefetch(0, buf0);
    #pragma unroll
    for (int k = 0; k < SPW; ++k) {
        float* ws = (k & 1) ? buf1 : buf0;
        if (k + 1 < SPW) {
            prefetch(k + 1, (k & 1) ? buf0 : buf1);
            __pipeline_wait_prior(1);              // group k complete
        } else {
            __pipeline_wait_prior(0);
        }
        __syncwarp();                              // cross-lane copies visible

        const int seg  = wid * SPW + k;
        const int base = seg * SEG;
        const int off0 = base - 32;
        if (seg >= 1 && seg <= 22)
            compute_fast(ws, lane, c, outr, off0);
        else
            compute_generic(ws, lane, c, outr, base, off0);
        __syncwarp();
    }
}

extern "C" void kernel_launch(void* const* d_in, const int* in_sizes, int n_in,
                              void* d_out, int out_size) {
    const float* x = (const float*)d_in[0];
    const float* b = (const float*)d_in[1];
    const float* a = (const float*)d_in[2];
    float* out = (float*)d_out;

    filtfilt_kernel<<<ROWS, THREADS>>>(x, b, a, out);
}